// round 3
// baseline (speedup 1.0000x reference)
#include <cuda_runtime.h>
#include <math.h>

// x: [16, 4, 2048, 257] fp32 -> BM=64 independent series-groups, T=2048, F=257
#define BM_      64
#define T_       2048
#define F_       257
#define CLEN     256
#define NCH      (T_ / CLEN)     // 8 chunks per series
#define LOOKBACK 384             // (1-s)^384 ~ 6e-5 << 1e-3 tolerance
#define NTHREADS 288
#define EPS_     1e-6f

__device__ __forceinline__ float lg2f(float v) { float r; asm("lg2.approx.f32 %0, %1;" : "=f"(r) : "f"(v)); return r; }
__device__ __forceinline__ float ex2f(float v) { float r; asm("ex2.approx.f32 %0, %1;" : "=f"(r) : "f"(v)); return r; }
__device__ __forceinline__ float rsqf(float v) { float r; asm("rsqrt.approx.f32 %0, %1;" : "=f"(r) : "f"(v)); return r; }

__global__ __launch_bounds__(NTHREADS, 4)
void pcen_kernel(const float* __restrict__ x,
                 const float* __restrict__ s_p,
                 const float* __restrict__ alpha_p,
                 const float* __restrict__ delta_p,
                 const float* __restrict__ r_p,
                 float* __restrict__ out) {
    const int c  = blockIdx.x & (NCH - 1);   // chunk along T (fast-varying -> SM balance)
    const int bm = blockIdx.x >> 3;          // series group
    const int f  = threadIdx.x;
    if (f >= F_) return;

    const float s     = s_p[0];
    const float alpha = alpha_p[0];
    const float delta = delta_p[0];
    const float r     = r_p[0];
    const float oms   = 1.0f - s;

    const int t0     = c * CLEN;
    const int tstart = (t0 > LOOKBACK) ? (t0 - LOOKBACK) : 0;

    const float* xb = x   + (size_t)bm * T_ * F_ + f;
    float*       ob = out + (size_t)bm * T_ * F_ + f;

    // ---- Warmup: EMA from tstart to t0 (exact if tstart==0, else truncated) ----
    float m = 0.0f;
    int t = tstart;
    if (t0 > 0 && tstart == 0) { m = xb[0]; t = 1; }   // exact initial condition M_0 = x_0
#pragma unroll 8
    for (; t < t0; t++)
        m = fmaf(oms, m, s * xb[(size_t)t * F_]);

    // ---- Output: continue EMA, apply PCEN nonlinearity, stream results ----
    const bool  half = (r == 0.5f);
    const float dr   = half ? sqrtf(delta) : ex2f(r * lg2f(delta));

    int i = 0;
    if (c == 0) {                            // first frame: M_0 = x_0
        const float xv = xb[0];
        m = xv;
        const float pw = ex2f(-alpha * lg2f(m + EPS_));
        const float u  = fmaf(xv, pw, delta);
        ob[0] = half ? fmaf(u, rsqf(u), -dr) : (ex2f(r * lg2f(u)) - dr);
        i = 1;
    }
#pragma unroll 4
    for (; i < CLEN; i++) {
        const size_t off = (size_t)(t0 + i) * F_;
        const float xv = xb[off];
        m = fmaf(oms, m, s * xv);
        const float pw = ex2f(-alpha * lg2f(m + EPS_));   // (M+eps)^(-alpha)
        const float u  = fmaf(xv, pw, delta);
        const float o  = half ? fmaf(u, rsqf(u), -dr)     // sqrt(u) = u * rsqrt(u)
                              : (ex2f(r * lg2f(u)) - dr);
        ob[off] = o;
    }
}

extern "C" void kernel_launch(void* const* d_in, const int* in_sizes, int n_in,
                              void* d_out, int out_size) {
    const float* x     = (const float*)d_in[0];
    const float* s     = (const float*)d_in[1];
    const float* alpha = (const float*)d_in[2];
    const float* delta = (const float*)d_in[3];
    const float* r     = (const float*)d_in[4];
    float* out = (float*)d_out;

    (void)in_sizes; (void)n_in; (void)out_size;

    pcen_kernel<<<BM_ * NCH, NTHREADS>>>(x, s, alpha, delta, r, out);
}

// round 5
// speedup vs baseline: 1.2975x; 1.2975x over previous
#include <cuda_runtime.h>
#include <math.h>

// x: [16, 4, 2048, 257] fp32 -> BM=64 series-groups, T=2048, F=257
#define BM_      64
#define T_       2048
#define F_       257
#define CLEN     32                 // frames per chunk
#define NCH      (T_ / CLEN)        // 64 chunks per series
#define NTHREADS 288                // 9 warps; threads [0,257) active
#define EPS_     1e-6f

// Published prefix-EMA tail per (bm, chunk, f). Poisoned to -1 each launch;
// all legal values >= 0 (x is uniform[0,1)), so the value itself is the flag.
// 64*64*257*4 = 4.2 MB -> L2-resident.
__device__ float        g_mend[BM_ * NCH * F_];
__device__ unsigned int g_ticket;

__global__ void pcen_reset_kernel() {
    int n = BM_ * NCH * F_;
    int i = blockIdx.x * blockDim.x + threadIdx.x;
    if (i == 0) g_ticket = 0u;
    for (; i < n; i += gridDim.x * blockDim.x) g_mend[i] = -1.0f;
}

__device__ __forceinline__ float ld_relaxed_gpu(const float* p) {
    float v;
    asm volatile("ld.relaxed.gpu.f32 %0, [%1];" : "=f"(v) : "l"(p));
    return v;
}
__device__ __forceinline__ void st_relaxed_gpu(float* p, float v) {
    asm volatile("st.relaxed.gpu.f32 [%0], %1;" :: "l"(p), "f"(v));
}
__device__ __forceinline__ float lg2f(float v) { float r; asm("lg2.approx.f32 %0, %1;" : "=f"(r) : "f"(v)); return r; }
__device__ __forceinline__ float ex2f(float v) { float r; asm("ex2.approx.f32 %0, %1;" : "=f"(r) : "f"(v)); return r; }
__device__ __forceinline__ float rsqf(float v) { float r; asm("rsqrt.approx.f32 %0, %1;" : "=f"(r) : "f"(v)); return r; }

__global__ __launch_bounds__(NTHREADS, 4)
void pcen_kernel(const float* __restrict__ x,
                 const float* __restrict__ s_p,
                 const float* __restrict__ alpha_p,
                 const float* __restrict__ delta_p,
                 const float* __restrict__ r_p,
                 float* __restrict__ out) {
    // Thread-private stash of this block's x-chunk: each thread writes/reads
    // only its own f column -> NO syncs needed. 32.9 KB static smem.
    __shared__ float sx[CLEN][F_];

    // Ticket-order virtualization: a waiter's predecessor always holds a
    // smaller ticket -> resident or finished -> deadlock-free across waves.
    __shared__ unsigned int s_vb;
    if (threadIdx.x == 0) s_vb = atomicAdd(&g_ticket, 1u);
    __syncthreads();
    const unsigned int vb = s_vb;
    const int bm = (int)(vb & (BM_ - 1));   // fast-varying: all 64 bm chains advance per wave
    const int c  = (int)(vb >> 6);          // chunk index along T

    const int f = threadIdx.x;
    if (f >= F_) return;

    const float s     = s_p[0];
    const float alpha = alpha_p[0];
    const float delta = delta_p[0];
    const float r     = r_p[0];
    const float oms   = 1.0f - s;

    const size_t base = ((size_t)bm * T_ + (size_t)c * CLEN) * F_ + f;
    const float* xp = x + base;

    // ---- Phase 0+1: stream chunk into smem, computing zero-init local EMA ----
    float m;
    {
        const float x0 = xp[0];
        sx[0][f] = x0;
        m = (c == 0) ? x0 : (s * x0);        // chunk 0: exact M_0 = x_0
#pragma unroll
        for (int i = 1; i < CLEN; i++) {
            const float xv = xp[(size_t)i * F_];
            sx[i][f] = xv;
            m = fmaf(oms, m, s * xv);
        }
    }

    // ---- Phase 2: chain combine. Per-f spin on predecessor's published tail. ----
    float m_in = 0.0f;
    if (c > 0) {
        float D = oms;                       // (1-s)^32 by repeated squaring
#pragma unroll
        for (int k = 0; k < 5; k++) D *= D;
        const float* prev = &g_mend[((size_t)bm * NCH + (size_t)(c - 1)) * F_ + f];
        float v;
        do { v = ld_relaxed_gpu(prev); } while (v < 0.0f);
        m_in = v;
        m = fmaf(D, m_in, m);                // full prefix tail for this chunk
    }
    st_relaxed_gpu(&g_mend[((size_t)bm * NCH + (size_t)c) * F_ + f], m);

    // ---- Phase 3: replay exact recurrence from m_in, emit PCEN output ----
    const bool  half = (r == 0.5f);
    const float dr   = half ? sqrtf(delta) : ex2f(r * lg2f(delta));

    float* op = out + base;
    float mm = m_in;
#pragma unroll
    for (int i = 0; i < CLEN; i++) {
        const float xv = sx[i][f];
        mm = (c == 0 && i == 0) ? xv : fmaf(oms, mm, s * xv);
        // (x / (mm+eps)^alpha + delta)^r - delta^r
        const float pw = ex2f(-alpha * lg2f(mm + EPS_));
        const float u  = fmaf(xv, pw, delta);
        const float o  = half ? fmaf(u, rsqf(u), -dr)    // sqrt(u) = u*rsqrt(u)
                              : (ex2f(r * lg2f(u)) - dr);
        op[(size_t)i * F_] = o;
    }
}

extern "C" void kernel_launch(void* const* d_in, const int* in_sizes, int n_in,
                              void* d_out, int out_size) {
    const float* x     = (const float*)d_in[0];
    const float* s     = (const float*)d_in[1];
    const float* alpha = (const float*)d_in[2];
    const float* delta = (const float*)d_in[3];
    const float* r     = (const float*)d_in[4];
    float* out = (float*)d_out;

    (void)in_sizes; (void)n_in; (void)out_size;

    pcen_reset_kernel<<<1024, 256>>>();                // re-poison scratch + ticket
    pcen_kernel<<<BM_ * NCH, NTHREADS>>>(x, s, alpha, delta, r, out);
}